// round 2
// baseline (speedup 1.0000x reference)
#include <cuda_runtime.h>
#include <math.h>

// NT-Xent loss, B=4096, D=128, N=8192, T=0.5
//   norm_kernel : L2-normalize z_i / z_j, store K-major Zt[k][row]
//   sim_kernel  : 128 blocks x 64 rows; sweep 128 col-tiles of 64.
//                 Fused GEMM + exp-sum epilogue with FIXED offset 2.0
//                 (rows normalized -> s in [-2,2], no online max needed).
//   finish_kernel: reduce 128 partials -> mean -> d_out[0]

#define NB   4096
#define NN   8192
#define DD   128
#define INV_T 2.0f
#define SOFF  2.0f

__device__ float g_Zt[DD * NN];      // K-major: g_Zt[k*NN + row]
__device__ float g_partial[128];

__global__ void norm_kernel(const float* __restrict__ zi,
                            const float* __restrict__ zj) {
    int warp = (blockIdx.x * blockDim.x + threadIdx.x) >> 5;   // one warp per row
    int lane = threadIdx.x & 31;
    if (warp >= NN) return;
    const float* src = (warp < NB) ? (zi + (size_t)warp * DD)
                                   : (zj + (size_t)(warp - NB) * DD);
    float4 v = ((const float4*)src)[lane];                     // 32 lanes * 4 = 128
    float ss = v.x*v.x + v.y*v.y + v.z*v.z + v.w*v.w;
    #pragma unroll
    for (int o = 16; o; o >>= 1) ss += __shfl_xor_sync(0xffffffffu, ss, o);
    float inv = 1.0f / fmaxf(sqrtf(ss), 1e-12f);
    int k = lane * 4;
    g_Zt[(k + 0) * NN + warp] = v.x * inv;
    g_Zt[(k + 1) * NN + warp] = v.y * inv;
    g_Zt[(k + 2) * NN + warp] = v.z * inv;
    g_Zt[(k + 3) * NN + warp] = v.w * inv;
}

// 256 threads as (tx 0..15, ty 0..15); 4x4 microtile; K-major shared tiles:
// As[k][64] / Bs[k][64] -> inner-loop LDS is broadcast (A) + contiguous (B).
__global__ void __launch_bounds__(256, 1) sim_kernel() {
    extern __shared__ float sm[];
    float* As = sm;              // [128][64]
    float* Bs = sm + DD * 64;    // [128][64]
    __shared__ float pos_s[64];
    __shared__ float ty_part[16];

    int tid = threadIdx.x;
    int tx = tid & 15, ty = tid >> 4;
    int r0 = blockIdx.x * 64;

    // Load A tile (K-major, coalesced float4)
    for (int i = tid; i < DD * 16; i += 256) {       // 2048 float4
        int k = i >> 4, r4 = i & 15;
        ((float4*)As)[i] = ((const float4*)g_Zt)[(size_t)k * (NN/4) + (r0 >> 2) + r4];
    }

    float rowsum[4] = {0.f, 0.f, 0.f, 0.f};

    for (int ct = 0; ct < NN / 64; ct++) {
        int c0 = ct * 64;
        __syncthreads();                              // prev tile compute done
        for (int i = tid; i < DD * 16; i += 256) {
            int k = i >> 4, r4 = i & 15;
            ((float4*)Bs)[i] = ((const float4*)g_Zt)[(size_t)k * (NN/4) + (c0 >> 2) + r4];
        }
        __syncthreads();

        float acc[4][4];
        #pragma unroll
        for (int i = 0; i < 4; i++)
            #pragma unroll
            for (int j = 0; j < 4; j++) acc[i][j] = 0.f;

        #pragma unroll 8
        for (int k = 0; k < DD; k++) {
            float4 a = ((const float4*)As)[k * 16 + ty];
            float4 b = ((const float4*)Bs)[k * 16 + tx];
            acc[0][0] += a.x*b.x; acc[0][1] += a.x*b.y; acc[0][2] += a.x*b.z; acc[0][3] += a.x*b.w;
            acc[1][0] += a.y*b.x; acc[1][1] += a.y*b.y; acc[1][2] += a.y*b.z; acc[1][3] += a.y*b.w;
            acc[2][0] += a.z*b.x; acc[2][1] += a.z*b.y; acc[2][2] += a.z*b.z; acc[2][3] += a.z*b.w;
            acc[3][0] += a.w*b.x; acc[3][1] += a.w*b.y; acc[3][2] += a.w*b.z; acc[3][3] += a.w*b.w;
        }

        // epilogue: fused exp-sum + positive-pair capture + diagonal skip
        #pragma unroll
        for (int i = 0; i < 4; i++) {
            int grow = r0 + ty * 4 + i;
            int gpos = (grow + NB) & (NN - 1);
            #pragma unroll
            for (int j = 0; j < 4; j++) {
                int gc = c0 + tx * 4 + j;
                float s = acc[i][j] * INV_T;
                if (gc == gpos) pos_s[ty * 4 + i] = s;     // unique writer
                if (gc != grow) rowsum[i] += __expf(s - SOFF);
            }
        }
    }

    // reduce rowsum across tx (16-lane segments within warp)
    #pragma unroll
    for (int i = 0; i < 4; i++) {
        #pragma unroll
        for (int o = 8; o; o >>= 1)
            rowsum[i] += __shfl_xor_sync(0xffffffffu, rowsum[i], o, 16);
    }
    __syncthreads();   // pos_s writes visible

    if (tx == 0) {
        float t = 0.f;
        #pragma unroll
        for (int i = 0; i < 4; i++)
            t += -pos_s[ty * 4 + i] + SOFF + logf(rowsum[i]);
        ty_part[ty] = t;
    }
    __syncthreads();
    if (tid == 0) {
        float t = 0.f;
        #pragma unroll
        for (int y = 0; y < 16; y++) t += ty_part[y];
        g_partial[blockIdx.x] = t;
    }
}

__global__ void finish_kernel(float* __restrict__ out) {
    __shared__ float s[128];
    int t = threadIdx.x;
    s[t] = g_partial[t];
    __syncthreads();
    #pragma unroll
    for (int o = 64; o; o >>= 1) {
        if (t < o) s[t] += s[t + o];
        __syncthreads();
    }
    if (t == 0) out[0] = s[0] * (1.0f / (float)NN);
}

extern "C" void kernel_launch(void* const* d_in, const int* in_sizes, int n_in,
                              void* d_out, int out_size) {
    const float* zi = (const float*)d_in[0];
    const float* zj = (const float*)d_in[1];
    float* out = (float*)d_out;
    (void)in_sizes; (void)n_in; (void)out_size;

    (void)cudaFuncSetAttribute(sim_kernel,
                               cudaFuncAttributeMaxDynamicSharedMemorySize,
                               64 * 1024);

    norm_kernel<<<NN / 8, 256>>>(zi, zj);            // 8 warps/block, 1 row/warp
    sim_kernel<<<NN / 64, 256, 64 * 1024>>>();
    finish_kernel<<<1, 128>>>(out);
}

// round 6
// speedup vs baseline: 7.6893x; 7.6893x over previous
#include <cuda_runtime.h>
#include <cuda_bf16.h>
#include <cstdint>
#include <math.h>

// NT-Xent loss, B=4096, D=128, N=8192, T=0.5 — mma.sync bf16 (sm_103-target-legal)
//
// norm_kernel : L2-normalize rows -> bf16 row-major g_Zb[8192][128]; zero sums.
// sim_kernel  : 256 blocks = 128 row-panels(64 rows) x 2 col-halves(4096).
//               A (64x128) ldmatrix'd into registers once; sweep 32 B tiles
//               (128 cols) double-buffered via cp.async; m16n8k16 bf16 HMMA;
//               epilogue in registers: rowsum += ex2(C1*acc - C1) over ALL j.
// finish      : per row: self & pos via fp32 dots of bf16 rows;
//               loss_i = 2 + log(rowsum_i - self_i) - pos_i; atomicAdd.
// writeout    : out[0] = g_loss / N.

#define NB   4096
#define NN   8192
#define C1   2.8853900817779268f   // 2*log2(e)

__device__ __align__(16) unsigned char g_Zb[NN * 256];  // bf16 rows, 256B each
__device__ float g_rowsum[NN];
__device__ float g_loss;

// ---------- helpers ----------
static __device__ __forceinline__ uint32_t smem_u32(const void* p) {
    uint32_t a;
    asm("{ .reg .u64 t; cvta.to.shared.u64 t, %1; cvt.u32.u64 %0, t; }"
        : "=r"(a) : "l"(p));
    return a;
}
#define CP_ASYNC16(dst, src) \
    asm volatile("cp.async.cg.shared.global [%0], [%1], 16;" :: "r"(dst), "l"(src))
#define CP_COMMIT() asm volatile("cp.async.commit_group;")
#define CP_WAIT(n)  asm volatile("cp.async.wait_group %0;" :: "n"(n))

static __device__ __forceinline__ void ldm_x4(uint32_t& r0, uint32_t& r1,
                                              uint32_t& r2, uint32_t& r3,
                                              uint32_t addr) {
    asm volatile("ldmatrix.sync.aligned.m8n8.x4.shared.b16 {%0,%1,%2,%3}, [%4];"
                 : "=r"(r0), "=r"(r1), "=r"(r2), "=r"(r3) : "r"(addr));
}
static __device__ __forceinline__ void mma16816(float* c, const uint32_t* a,
                                                const uint32_t* b) {
    asm volatile(
        "mma.sync.aligned.m16n8k16.row.col.f32.bf16.bf16.f32 "
        "{%0,%1,%2,%3}, {%4,%5,%6,%7}, {%8,%9}, {%0,%1,%2,%3};"
        : "+f"(c[0]), "+f"(c[1]), "+f"(c[2]), "+f"(c[3])
        : "r"(a[0]), "r"(a[1]), "r"(a[2]), "r"(a[3]), "r"(b[0]), "r"(b[1]));
}
static __device__ __forceinline__ float ex2f(float x) {
    float r;
    asm("ex2.approx.f32 %0, %1;" : "=f"(r) : "f"(x));
    return r;
}

// ---------- kernels ----------
__global__ void norm_kernel(const float* __restrict__ zi,
                            const float* __restrict__ zj) {
    int gt = blockIdx.x * blockDim.x + threadIdx.x;
    if (gt < NN) g_rowsum[gt] = 0.f;
    if (gt == 0) g_loss = 0.f;
    int row = gt >> 5;
    int lane = threadIdx.x & 31;
    if (row >= NN) return;
    const float* src = (row < NB) ? (zi + (size_t)row * 128)
                                  : (zj + (size_t)(row - NB) * 128);
    float4 v = ((const float4*)src)[lane];
    float ss = v.x*v.x + v.y*v.y + v.z*v.z + v.w*v.w;
    #pragma unroll
    for (int o = 16; o; o >>= 1) ss += __shfl_xor_sync(0xffffffffu, ss, o);
    float inv = 1.0f / fmaxf(sqrtf(ss), 1e-12f);
    __nv_bfloat162 p0 = __floats2bfloat162_rn(v.x * inv, v.y * inv);
    __nv_bfloat162 p1 = __floats2bfloat162_rn(v.z * inv, v.w * inv);
    uint2 pk;
    pk.x = *reinterpret_cast<uint32_t*>(&p0);
    pk.y = *reinterpret_cast<uint32_t*>(&p1);
    *reinterpret_cast<uint2*>(g_Zb + (size_t)row * 256 + lane * 8) = pk;
}

// 256 threads / 8 warps: warp tile 32 rows x 32 cols of the 64x128 block tile.
__global__ void __launch_bounds__(256, 1) sim_kernel() {
    extern __shared__ unsigned char smraw[];
    uint32_t s0 = smem_u32(smraw);
    uint32_t Bb[2] = { s0, s0 + 32768u };
    uint32_t Ab = s0 + 65536u;

    int tid = threadIdx.x, lane = tid & 31, w = tid >> 5;
    int wm = w & 1, wn = w >> 1;                 // warp grid 2m x 4n
    int rp = blockIdx.x >> 1, half = blockIdx.x & 1;
    int r0 = rp * 64;
    const unsigned char* Z = g_Zb;

    // stage A: 64 rows x 256B, chunk-XOR swizzle
    #pragma unroll
    for (int i = 0; i < 4; i++) {
        int idx = tid + i * 256;                 // 1024 chunks
        int row = idx >> 4, c = idx & 15;
        uint32_t dst = Ab + row * 256 + ((c ^ (row & 7)) * 16);
        CP_ASYNC16(dst, Z + (size_t)(r0 + row) * 256 + c * 16);
    }
    CP_COMMIT();

    // prefetch B tiles 0,1
    #pragma unroll
    for (int t = 0; t < 2; t++) {
        int cg0 = half * 4096 + t * 128;
        #pragma unroll
        for (int i = 0; i < 8; i++) {
            int idx = tid + i * 256;             // 2048 chunks
            int n = idx >> 4, c = idx & 15;
            uint32_t dst = Bb[t] + n * 256 + ((c ^ (n & 7)) * 16);
            CP_ASYNC16(dst, Z + (size_t)(cg0 + n) * 256 + c * 16);
        }
        CP_COMMIT();
    }

    // A fragments -> registers (2 m-atoms x 8 k-steps x 4 regs)
    CP_WAIT(2);
    __syncthreads();
    uint32_t Ar[2][8][4];
    {
        int row_loc = (lane & 7) + ((lane >> 3) & 1) * 8;
        int kpar = (lane >> 4) & 1;
        uint32_t abase = Ab + (uint32_t)(wm * 32 + row_loc) * 256u;
        #pragma unroll
        for (int ma = 0; ma < 2; ma++)
            #pragma unroll
            for (int ks = 0; ks < 8; ks++) {
                uint32_t addr = abase + (uint32_t)(ma * 16) * 256u
                              + (uint32_t)(((2 * ks + kpar) ^ (row_loc & 7)) * 16);
                ldm_x4(Ar[ma][ks][0], Ar[ma][ks][1], Ar[ma][ks][2], Ar[ma][ks][3], addr);
            }
    }

    // B ldmatrix lane geometry
    int n_loc = (lane & 7) + ((lane >> 4) << 3);     // 0..15
    int cpar = (lane >> 3) & 1;

    float rowacc[4] = {0.f, 0.f, 0.f, 0.f};

    for (int t = 0; t < 32; t++) {
        uint32_t buf = Bb[t & 1];
        CP_WAIT(1);
        __syncthreads();

        float acc[2][4][4];
        #pragma unroll
        for (int mi = 0; mi < 2; mi++)
            #pragma unroll
            for (int ni = 0; ni < 4; ni++)
                #pragma unroll
                for (int e = 0; e < 4; e++) acc[mi][ni][e] = 0.f;

        #pragma unroll
        for (int ks = 0; ks < 8; ks++) {
            uint32_t bfr[8];
            #pragma unroll
            for (int pr = 0; pr < 2; pr++) {
                int n = wn * 32 + pr * 16 + n_loc;
                uint32_t addr = buf + (uint32_t)n * 256u
                              + (uint32_t)(((2 * ks + cpar) ^ (n_loc & 7)) * 16);
                ldm_x4(bfr[pr*4+0], bfr[pr*4+1], bfr[pr*4+2], bfr[pr*4+3], addr);
            }
            #pragma unroll
            for (int mi = 0; mi < 2; mi++) {
                mma16816(acc[mi][0], Ar[mi][ks], &bfr[0]);
                mma16816(acc[mi][1], Ar[mi][ks], &bfr[2]);
                mma16816(acc[mi][2], Ar[mi][ks], &bfr[4]);
                mma16816(acc[mi][3], Ar[mi][ks], &bfr[6]);
            }
        }
        __syncthreads();                          // everyone done reading buf

        if (t + 2 < 32) {                         // refill this buffer
            int cg0 = half * 4096 + (t + 2) * 128;
            #pragma unroll
            for (int i = 0; i < 8; i++) {
                int idx = tid + i * 256;
                int n = idx >> 4, c = idx & 15;
                uint32_t dst = buf + n * 256 + ((c ^ (n & 7)) * 16);
                CP_ASYNC16(dst, Z + (size_t)(cg0 + n) * 256 + c * 16);
            }
        }
        CP_COMMIT();                              // commit (possibly empty) group

        // epilogue: rowsum += exp(2*acc - 2), all j (self fixed in finish)
        #pragma unroll
        for (int mi = 0; mi < 2; mi++) {
            float t0 = 0.f, t1 = 0.f;
            #pragma unroll
            for (int ni = 0; ni < 4; ni++) {
                t0 += ex2f(fmaf(acc[mi][ni][0], C1, -C1));
                t0 += ex2f(fmaf(acc[mi][ni][1], C1, -C1));
                t1 += ex2f(fmaf(acc[mi][ni][2], C1, -C1));
                t1 += ex2f(fmaf(acc[mi][ni][3], C1, -C1));
            }
            rowacc[mi * 2 + 0] += t0;
            rowacc[mi * 2 + 1] += t1;
        }
    }

    // reduce within quad (lanes sharing a row), then atomicAdd
    #pragma unroll
    for (int k = 0; k < 4; k++) {
        rowacc[k] += __shfl_xor_sync(0xffffffffu, rowacc[k], 1);
        rowacc[k] += __shfl_xor_sync(0xffffffffu, rowacc[k], 2);
    }
    if ((lane & 3) == 0) {
        int rbase = r0 + wm * 32 + (lane >> 2);
        atomicAdd(&g_rowsum[rbase],      rowacc[0]);
        atomicAdd(&g_rowsum[rbase + 8],  rowacc[1]);
        atomicAdd(&g_rowsum[rbase + 16], rowacc[2]);
        atomicAdd(&g_rowsum[rbase + 24], rowacc[3]);
    }
}

// one warp per row: self & positive dots, per-row loss, block-reduced atomicAdd
__global__ void finish_kernel() {
    __shared__ float sh[8];
    int tid = threadIdx.x, lane = tid & 31, w = tid >> 5;
    int i = blockIdx.x * 8 + w;
    int j = (i + NB) & (NN - 1);
    uint2 ua = *reinterpret_cast<const uint2*>(g_Zb + (size_t)i * 256 + lane * 8);
    uint2 ub = *reinterpret_cast<const uint2*>(g_Zb + (size_t)j * 256 + lane * 8);
    float2 a0 = __bfloat1622float2(*reinterpret_cast<__nv_bfloat162*>(&ua.x));
    float2 a1 = __bfloat1622float2(*reinterpret_cast<__nv_bfloat162*>(&ua.y));
    float2 b0 = __bfloat1622float2(*reinterpret_cast<__nv_bfloat162*>(&ub.x));
    float2 b1 = __bfloat1622float2(*reinterpret_cast<__nv_bfloat162*>(&ub.y));
    float sd = a0.x*a0.x + a0.y*a0.y + a1.x*a1.x + a1.y*a1.y;
    float pd = a0.x*b0.x + a0.y*b0.y + a1.x*b1.x + a1.y*b1.y;
    #pragma unroll
    for (int o = 16; o; o >>= 1) {
        sd += __shfl_xor_sync(0xffffffffu, sd, o);
        pd += __shfl_xor_sync(0xffffffffu, pd, o);
    }
    float loss = 0.f;
    if (lane == 0) {
        float self = ex2f(fmaf(sd, C1, -C1));
        loss = 2.0f + logf(g_rowsum[i] - self) - 2.0f * pd;
        sh[w] = loss;
    }
    __syncthreads();
    if (tid == 0) {
        float t = 0.f;
        #pragma unroll
        for (int k = 0; k < 8; k++) t += sh[k];
        atomicAdd(&g_loss, t);
    }
}

__global__ void writeout_kernel(float* __restrict__ out) {
    out[0] = g_loss * (1.0f / (float)NN);
}

extern "C" void kernel_launch(void* const* d_in, const int* in_sizes, int n_in,
                              void* d_out, int out_size) {
    const float* zi = (const float*)d_in[0];
    const float* zj = (const float*)d_in[1];
    float* out = (float*)d_out;
    (void)in_sizes; (void)n_in; (void)out_size;

    (void)cudaFuncSetAttribute(sim_kernel,
                               cudaFuncAttributeMaxDynamicSharedMemorySize,
                               81920);

    norm_kernel<<<1024, 256>>>(zi, zj);
    sim_kernel<<<256, 256, 81920>>>();
    finish_kernel<<<NN / 8, 256>>>();
    writeout_kernel<<<1, 1>>>(out);
}

// round 9
// speedup vs baseline: 8.5985x; 1.1182x over previous
#include <cuda_runtime.h>
#include <cuda_bf16.h>
#include <cstdint>
#include <math.h>

// NT-Xent loss, B=4096, D=128, N=8192, T=0.5 — mma.sync bf16
// R7: 128-row panels (128 blocks, 1 wave, half L2 traffic), fused writeout,
//     self-dot precomputed in norm.

#define NB   4096
#define NN   8192
#define C1   2.8853900817779268f   // 2*log2(e)

__device__ __align__(16) unsigned char g_Zb[NN * 256];  // bf16 rows, 256B each
__device__ float g_rowsum[NN];
__device__ float g_self[NN];
__device__ float g_loss;
__device__ unsigned int g_done;

// ---------- helpers ----------
static __device__ __forceinline__ uint32_t smem_u32(const void* p) {
    uint32_t a;
    asm("{ .reg .u64 t; cvta.to.shared.u64 t, %1; cvt.u32.u64 %0, t; }"
        : "=r"(a) : "l"(p));
    return a;
}
#define CP_ASYNC16(dst, src) \
    asm volatile("cp.async.cg.shared.global [%0], [%1], 16;" :: "r"(dst), "l"(src))
#define CP_COMMIT() asm volatile("cp.async.commit_group;")
#define CP_WAIT(n)  asm volatile("cp.async.wait_group %0;" :: "n"(n))

static __device__ __forceinline__ void ldm_x4(uint32_t& r0, uint32_t& r1,
                                              uint32_t& r2, uint32_t& r3,
                                              uint32_t addr) {
    asm volatile("ldmatrix.sync.aligned.m8n8.x4.shared.b16 {%0,%1,%2,%3}, [%4];"
                 : "=r"(r0), "=r"(r1), "=r"(r2), "=r"(r3) : "r"(addr));
}
static __device__ __forceinline__ void mma16816(float* c, const uint32_t* a,
                                                const uint32_t* b) {
    asm volatile(
        "mma.sync.aligned.m16n8k16.row.col.f32.bf16.bf16.f32 "
        "{%0,%1,%2,%3}, {%4,%5,%6,%7}, {%8,%9}, {%0,%1,%2,%3};"
        : "+f"(c[0]), "+f"(c[1]), "+f"(c[2]), "+f"(c[3])
        : "r"(a[0]), "r"(a[1]), "r"(a[2]), "r"(a[3]), "r"(b[0]), "r"(b[1]));
}
static __device__ __forceinline__ float ex2f(float x) {
    float r;
    asm("ex2.approx.f32 %0, %1;" : "=f"(r) : "f"(x));
    return r;
}

// ---------- kernels ----------
__global__ void norm_kernel(const float* __restrict__ zi,
                            const float* __restrict__ zj) {
    int gt = blockIdx.x * blockDim.x + threadIdx.x;
    if (gt < NN) g_rowsum[gt] = 0.f;
    if (gt == 0) { g_loss = 0.f; g_done = 0u; }
    int row = gt >> 5;
    int lane = threadIdx.x & 31;
    if (row >= NN) return;
    const float* src = (row < NB) ? (zi + (size_t)row * 128)
                                  : (zj + (size_t)(row - NB) * 128);
    float4 v = ((const float4*)src)[lane];
    float ss = v.x*v.x + v.y*v.y + v.z*v.z + v.w*v.w;
    #pragma unroll
    for (int o = 16; o; o >>= 1) ss += __shfl_xor_sync(0xffffffffu, ss, o);
    float inv = 1.0f / fmaxf(sqrtf(ss), 1e-12f);
    __nv_bfloat162 p0 = __floats2bfloat162_rn(v.x * inv, v.y * inv);
    __nv_bfloat162 p1 = __floats2bfloat162_rn(v.z * inv, v.w * inv);
    // self-dot of the bf16-rounded row (matches what the MMA diagonal computes)
    float2 q0 = __bfloat1622float2(p0);
    float2 q1 = __bfloat1622float2(p1);
    float sd = q0.x*q0.x + q0.y*q0.y + q1.x*q1.x + q1.y*q1.y;
    #pragma unroll
    for (int o = 16; o; o >>= 1) sd += __shfl_xor_sync(0xffffffffu, sd, o);
    if (lane == 0) g_self[row] = sd;
    uint2 pk;
    pk.x = *reinterpret_cast<uint32_t*>(&p0);
    pk.y = *reinterpret_cast<uint32_t*>(&p1);
    *reinterpret_cast<uint2*>(g_Zb + (size_t)row * 256 + lane * 8) = pk;
}

// 128 blocks = 64 row-panels(128 rows) x 2 col-halves(4096 cols); one wave.
// 8 warps: wm in [0,4) (32 rows each), wn in [0,2) (64 cols of each 128-col tile).
__global__ void __launch_bounds__(256, 1) sim_kernel() {
    extern __shared__ unsigned char smraw[];
    uint32_t s0 = smem_u32(smraw);
    uint32_t Bb[2] = { s0, s0 + 32768u };
    uint32_t Ab = s0 + 65536u;                   // 32KB A stage

    int tid = threadIdx.x, lane = tid & 31, w = tid >> 5;
    int wm = w & 3, wn = w >> 2;
    int rp = blockIdx.x >> 1, half = blockIdx.x & 1;
    int r0 = rp * 128;
    const unsigned char* Z = g_Zb;

    // stage A: 128 rows x 256B, chunk-XOR swizzle (2048 chunks, 8/thread)
    #pragma unroll
    for (int i = 0; i < 8; i++) {
        int idx = tid + i * 256;
        int row = idx >> 4, c = idx & 15;
        uint32_t dst = Ab + row * 256 + ((c ^ (row & 7)) * 16);
        CP_ASYNC16(dst, Z + (size_t)(r0 + row) * 256 + c * 16);
    }
    CP_COMMIT();

    // prefetch B tiles 0,1 (each 128 cols x 256B = 32KB)
    #pragma unroll
    for (int t = 0; t < 2; t++) {
        int cg0 = half * 4096 + t * 128;
        #pragma unroll
        for (int i = 0; i < 8; i++) {
            int idx = tid + i * 256;
            int n = idx >> 4, c = idx & 15;
            uint32_t dst = Bb[t] + n * 256 + ((c ^ (n & 7)) * 16);
            CP_ASYNC16(dst, Z + (size_t)(cg0 + n) * 256 + c * 16);
        }
        CP_COMMIT();
    }

    // A fragments -> registers (2 m-atoms x 8 k-steps x 4 regs)
    CP_WAIT(2);
    __syncthreads();
    uint32_t Ar[2][8][4];
    {
        int row_loc = (lane & 7) + ((lane >> 3) & 1) * 8;
        int kpar = (lane >> 4) & 1;
        uint32_t abase = Ab + (uint32_t)(wm * 32 + row_loc) * 256u;
        #pragma unroll
        for (int ma = 0; ma < 2; ma++)
            #pragma unroll
            for (int ks = 0; ks < 8; ks++) {
                uint32_t addr = abase + (uint32_t)(ma * 16) * 256u
                              + (uint32_t)(((2 * ks + kpar) ^ (row_loc & 7)) * 16);
                ldm_x4(Ar[ma][ks][0], Ar[ma][ks][1], Ar[ma][ks][2], Ar[ma][ks][3], addr);
            }
    }

    int n_loc = (lane & 7) + ((lane >> 4) << 3);
    int cpar = (lane >> 3) & 1;

    float rowacc[4] = {0.f, 0.f, 0.f, 0.f};

    for (int t = 0; t < 32; t++) {
        uint32_t buf = Bb[t & 1];
        CP_WAIT(1);
        __syncthreads();

        float acc[2][8][4];
        #pragma unroll
        for (int mi = 0; mi < 2; mi++)
            #pragma unroll
            for (int ni = 0; ni < 8; ni++)
                #pragma unroll
                for (int e = 0; e < 4; e++) acc[mi][ni][e] = 0.f;

        #pragma unroll
        for (int ks = 0; ks < 8; ks++) {
            uint32_t bfr[16];
            #pragma unroll
            for (int pr = 0; pr < 4; pr++) {
                int n = wn * 64 + pr * 16 + n_loc;
                uint32_t addr = buf + (uint32_t)n * 256u
                              + (uint32_t)(((2 * ks + cpar) ^ (n_loc & 7)) * 16);
                ldm_x4(bfr[pr*4+0], bfr[pr*4+1], bfr[pr*4+2], bfr[pr*4+3], addr);
            }
            #pragma unroll
            for (int mi = 0; mi < 2; mi++)
                #pragma unroll
                for (int pr = 0; pr < 4; pr++) {
                    mma16816(acc[mi][pr*2+0], Ar[mi][ks], &bfr[pr*4+0]);
                    mma16816(acc[mi][pr*2+1], Ar[mi][ks], &bfr[pr*4+2]);
                }
        }
        __syncthreads();                          // all warps done reading buf

        if (t + 2 < 32) {                         // refill this buffer
            int cg0 = half * 4096 + (t + 2) * 128;
            #pragma unroll
            for (int i = 0; i < 8; i++) {
                int idx = tid + i * 256;
                int n = idx >> 4, c = idx & 15;
                uint32_t dst = buf + n * 256 + ((c ^ (n & 7)) * 16);
                CP_ASYNC16(dst, Z + (size_t)(cg0 + n) * 256 + c * 16);
            }
        }
        CP_COMMIT();

        // epilogue over ALL j: rowsum += exp(2*acc - 2); self fixed in finish
        #pragma unroll
        for (int mi = 0; mi < 2; mi++) {
            float t0 = 0.f, t1 = 0.f;
            #pragma unroll
            for (int ni = 0; ni < 8; ni++) {
                t0 += ex2f(fmaf(acc[mi][ni][0], C1, -C1));
                t0 += ex2f(fmaf(acc[mi][ni][1], C1, -C1));
                t1 += ex2f(fmaf(acc[mi][ni][2], C1, -C1));
                t1 += ex2f(fmaf(acc[mi][ni][3], C1, -C1));
            }
            rowacc[mi * 2 + 0] += t0;
            rowacc[mi * 2 + 1] += t1;
        }
    }

    // reduce within quad (lanes sharing a row), then atomicAdd
    #pragma unroll
    for (int k = 0; k < 4; k++) {
        rowacc[k] += __shfl_xor_sync(0xffffffffu, rowacc[k], 1);
        rowacc[k] += __shfl_xor_sync(0xffffffffu, rowacc[k], 2);
    }
    if ((lane & 3) == 0) {
        int rbase = r0 + wm * 32 + (lane >> 2);
        atomicAdd(&g_rowsum[rbase],      rowacc[0]);
        atomicAdd(&g_rowsum[rbase + 8],  rowacc[1]);
        atomicAdd(&g_rowsum[rbase + 16], rowacc[2]);
        atomicAdd(&g_rowsum[rbase + 24], rowacc[3]);
    }
}

// one warp per row: positive dot, per-row loss, block reduce, fused writeout
__global__ void finish_kernel(float* __restrict__ out) {
    __shared__ float sh[8];
    int tid = threadIdx.x, lane = tid & 31, w = tid >> 5;
    int i = blockIdx.x * 8 + w;
    int j = (i + NB) & (NN - 1);
    uint2 ua = *reinterpret_cast<const uint2*>(g_Zb + (size_t)i * 256 + lane * 8);
    uint2 ub = *reinterpret_cast<const uint2*>(g_Zb + (size_t)j * 256 + lane * 8);
    float2 a0 = __bfloat1622float2(*reinterpret_cast<__nv_bfloat162*>(&ua.x));
    float2 a1 = __bfloat1622float2(*reinterpret_cast<__nv_bfloat162*>(&ua.y));
    float2 b0 = __bfloat1622float2(*reinterpret_cast<__nv_bfloat162*>(&ub.x));
    float2 b1 = __bfloat1622float2(*reinterpret_cast<__nv_bfloat162*>(&ub.y));
    float pd = a0.x*b0.x + a0.y*b0.y + a1.x*b1.x + a1.y*b1.y;
    #pragma unroll
    for (int o = 16; o; o >>= 1) pd += __shfl_xor_sync(0xffffffffu, pd, o);
    if (lane == 0) {
        float self = ex2f(fmaf(g_self[i], C1, -C1));
        sh[w] = 2.0f + logf(g_rowsum[i] - self) - 2.0f * pd;
    }
    __syncthreads();
    if (tid == 0) {
        float t = 0.f;
        #pragma unroll
        for (int k = 0; k < 8; k++) t += sh[k];
        atomicAdd(&g_loss, t);
        __threadfence();
        unsigned int done = atomicAdd(&g_done, 1u);
        if (done == (unsigned int)(gridDim.x - 1)) {
            out[0] = g_loss * (1.0f / (float)NN);
        }
    }
}

extern "C" void kernel_launch(void* const* d_in, const int* in_sizes, int n_in,
                              void* d_out, int out_size) {
    const float* zi = (const float*)d_in[0];
    const float* zj = (const float*)d_in[1];
    float* out = (float*)d_out;
    (void)in_sizes; (void)n_in; (void)out_size;

    (void)cudaFuncSetAttribute(sim_kernel,
                               cudaFuncAttributeMaxDynamicSharedMemorySize,
                               98304);

    norm_kernel<<<1024, 256>>>(zi, zj);
    sim_kernel<<<128, 256, 98304>>>();
    finish_kernel<<<NN / 8, 256>>>(out);
}

// round 11
// speedup vs baseline: 9.1977x; 1.0697x over previous
#include <cuda_runtime.h>
#include <cuda_bf16.h>
#include <cstdint>
#include <math.h>

// NT-Xent loss, B=4096, D=128, N=8192, T=0.5 — mma.sync bf16
// R10 (resubmit): interleave MUFU epilogue (ex2) of the previous 32-col
// half-tile with the HMMA stream of the current half-tile (ping-pong
// accumulators), so tensor and MUFU pipes overlap instead of convoying.

#define NB   4096
#define NN   8192
#define C1   2.8853900817779268f   // 2*log2(e)

__device__ __align__(16) unsigned char g_Zb[NN * 256];  // bf16 rows, 256B each
__device__ float g_rowsum[NN];
__device__ float g_self[NN];
__device__ float g_loss;
__device__ unsigned int g_done;

// ---------- helpers ----------
static __device__ __forceinline__ uint32_t smem_u32(const void* p) {
    uint32_t a;
    asm("{ .reg .u64 t; cvta.to.shared.u64 t, %1; cvt.u32.u64 %0, t; }"
        : "=r"(a) : "l"(p));
    return a;
}
#define CP_ASYNC16(dst, src) \
    asm volatile("cp.async.cg.shared.global [%0], [%1], 16;" :: "r"(dst), "l"(src))
#define CP_COMMIT() asm volatile("cp.async.commit_group;")
#define CP_WAIT(n)  asm volatile("cp.async.wait_group %0;" :: "n"(n))

static __device__ __forceinline__ void ldm_x4(uint32_t& r0, uint32_t& r1,
                                              uint32_t& r2, uint32_t& r3,
                                              uint32_t addr) {
    asm volatile("ldmatrix.sync.aligned.m8n8.x4.shared.b16 {%0,%1,%2,%3}, [%4];"
                 : "=r"(r0), "=r"(r1), "=r"(r2), "=r"(r3) : "r"(addr));
}
static __device__ __forceinline__ void mma16816(float* c, const uint32_t* a,
                                                const uint32_t* b) {
    asm volatile(
        "mma.sync.aligned.m16n8k16.row.col.f32.bf16.bf16.f32 "
        "{%0,%1,%2,%3}, {%4,%5,%6,%7}, {%8,%9}, {%0,%1,%2,%3};"
        : "+f"(c[0]), "+f"(c[1]), "+f"(c[2]), "+f"(c[3])
        : "r"(a[0]), "r"(a[1]), "r"(a[2]), "r"(a[3]), "r"(b[0]), "r"(b[1]));
}
static __device__ __forceinline__ float ex2f(float x) {
    float r;
    asm("ex2.approx.f32 %0, %1;" : "=f"(r) : "f"(x));
    return r;
}

// One 32-col half-step: fill acc[32] with MMA over K=128 while draining the
// epilogue of epi[32] (4 ex2 per k-step, interleaved into the HMMA stream).
static __device__ __forceinline__ void half_step(
    float* __restrict__ acc, float* __restrict__ epi, float* __restrict__ rowacc,
    uint32_t buf, int ncol0, int n_loc, int cpar, const uint32_t (*Ar)[8][4])
{
    #pragma unroll
    for (int f = 0; f < 32; f++) acc[f] = 0.f;
    #pragma unroll
    for (int ks = 0; ks < 8; ks++) {
        uint32_t bfr[8];
        #pragma unroll
        for (int pr = 0; pr < 2; pr++) {
            int n = ncol0 + pr * 16 + n_loc;
            uint32_t addr = buf + (uint32_t)n * 256u
                          + (uint32_t)(((2 * ks + cpar) ^ (n_loc & 7)) * 16);
            ldm_x4(bfr[pr*4+0], bfr[pr*4+1], bfr[pr*4+2], bfr[pr*4+3], addr);
        }
        #pragma unroll
        for (int mi = 0; mi < 2; mi++) {
            mma16816(&acc[mi*16 + 0],  Ar[mi][ks], &bfr[0]);
            mma16816(&acc[mi*16 + 4],  Ar[mi][ks], &bfr[2]);
            mma16816(&acc[mi*16 + 8],  Ar[mi][ks], &bfr[4]);
            mma16816(&acc[mi*16 + 12], Ar[mi][ks], &bfr[6]);
        }
        // drain 4 epilogue terms of the PREVIOUS half (independent of acc)
        #pragma unroll
        for (int u = 0; u < 4; u++) {
            int f = ks * 4 + u;
            rowacc[((f >> 4) << 1) | ((f & 3) >> 1)]
                += ex2f(fmaf(epi[f], C1, -C1));
        }
    }
}

// ---------- kernels ----------
__global__ void norm_kernel(const float* __restrict__ zi,
                            const float* __restrict__ zj) {
    int gt = blockIdx.x * blockDim.x + threadIdx.x;
    if (gt < NN) g_rowsum[gt] = 0.f;
    if (gt == 0) { g_loss = 0.f; g_done = 0u; }
    int row = gt >> 5;
    int lane = threadIdx.x & 31;
    if (row >= NN) return;
    const float* src = (row < NB) ? (zi + (size_t)row * 128)
                                  : (zj + (size_t)(row - NB) * 128);
    float4 v = ((const float4*)src)[lane];
    float ss = v.x*v.x + v.y*v.y + v.z*v.z + v.w*v.w;
    #pragma unroll
    for (int o = 16; o; o >>= 1) ss += __shfl_xor_sync(0xffffffffu, ss, o);
    float inv = 1.0f / fmaxf(sqrtf(ss), 1e-12f);
    __nv_bfloat162 p0 = __floats2bfloat162_rn(v.x * inv, v.y * inv);
    __nv_bfloat162 p1 = __floats2bfloat162_rn(v.z * inv, v.w * inv);
    float2 q0 = __bfloat1622float2(p0);
    float2 q1 = __bfloat1622float2(p1);
    float sd = q0.x*q0.x + q0.y*q0.y + q1.x*q1.x + q1.y*q1.y;
    #pragma unroll
    for (int o = 16; o; o >>= 1) sd += __shfl_xor_sync(0xffffffffu, sd, o);
    if (lane == 0) g_self[row] = sd;
    uint2 pk;
    pk.x = *reinterpret_cast<uint32_t*>(&p0);
    pk.y = *reinterpret_cast<uint32_t*>(&p1);
    *reinterpret_cast<uint2*>(g_Zb + (size_t)row * 256 + lane * 8) = pk;
}

// 128 blocks = 64 row-panels(128 rows) x 2 col-halves(4096 cols); one wave.
__global__ void __launch_bounds__(256, 1) sim_kernel() {
    extern __shared__ unsigned char smraw[];
    uint32_t s0 = smem_u32(smraw);
    uint32_t Bb[2] = { s0, s0 + 32768u };
    uint32_t Ab = s0 + 65536u;

    int tid = threadIdx.x, lane = tid & 31, w = tid >> 5;
    int wm = w & 3, wn = w >> 2;
    int rp = blockIdx.x >> 1, half = blockIdx.x & 1;
    int r0 = rp * 128;
    const unsigned char* Z = g_Zb;

    #pragma unroll
    for (int i = 0; i < 8; i++) {                // stage A: 128 rows x 256B
        int idx = tid + i * 256;
        int row = idx >> 4, c = idx & 15;
        uint32_t dst = Ab + row * 256 + ((c ^ (row & 7)) * 16);
        CP_ASYNC16(dst, Z + (size_t)(r0 + row) * 256 + c * 16);
    }
    CP_COMMIT();

    #pragma unroll
    for (int t = 0; t < 2; t++) {                // prefetch B tiles 0,1
        int cg0 = half * 4096 + t * 128;
        #pragma unroll
        for (int i = 0; i < 8; i++) {
            int idx = tid + i * 256;
            int n = idx >> 4, c = idx & 15;
            uint32_t dst = Bb[t] + n * 256 + ((c ^ (n & 7)) * 16);
            CP_ASYNC16(dst, Z + (size_t)(cg0 + n) * 256 + c * 16);
        }
        CP_COMMIT();
    }

    CP_WAIT(2);
    __syncthreads();
    uint32_t Ar[2][8][4];
    {
        int row_loc = (lane & 7) + ((lane >> 3) & 1) * 8;
        int kpar = (lane >> 4) & 1;
        uint32_t abase = Ab + (uint32_t)(wm * 32 + row_loc) * 256u;
        #pragma unroll
        for (int ma = 0; ma < 2; ma++)
            #pragma unroll
            for (int ks = 0; ks < 8; ks++) {
                uint32_t addr = abase + (uint32_t)(ma * 16) * 256u
                              + (uint32_t)(((2 * ks + kpar) ^ (row_loc & 7)) * 16);
                ldm_x4(Ar[ma][ks][0], Ar[ma][ks][1], Ar[ma][ks][2], Ar[ma][ks][3], addr);
            }
    }

    int n_loc = (lane & 7) + ((lane >> 4) << 3);
    int cpar = (lane >> 3) & 1;

    float rowacc[4] = {0.f, 0.f, 0.f, 0.f};
    float accA[32], accB[32];
    #pragma unroll
    for (int f = 0; f < 32; f++) accB[f] = -__int_as_float(0x7f800000);  // -inf

    for (int t = 0; t < 32; t++) {
        uint32_t buf = Bb[t & 1];
        CP_WAIT(1);
        __syncthreads();

        int nbase = wn * 64;
        half_step(accA, accB, rowacc, buf, nbase,      n_loc, cpar, Ar);
        half_step(accB, accA, rowacc, buf, nbase + 32, n_loc, cpar, Ar);

        __syncthreads();                          // all warps done reading buf
        if (t + 2 < 32) {
            int cg0 = half * 4096 + (t + 2) * 128;
            #pragma unroll
            for (int i = 0; i < 8; i++) {
                int idx = tid + i * 256;
                int n = idx >> 4, c = idx & 15;
                uint32_t dst = buf + n * 256 + ((c ^ (n & 7)) * 16);
                CP_ASYNC16(dst, Z + (size_t)(cg0 + n) * 256 + c * 16);
            }
        }
        CP_COMMIT();
    }

    // flush final half
    #pragma unroll
    for (int f = 0; f < 32; f++)
        rowacc[((f >> 4) << 1) | ((f & 3) >> 1)] += ex2f(fmaf(accB[f], C1, -C1));

    #pragma unroll
    for (int k = 0; k < 4; k++) {
        rowacc[k] += __shfl_xor_sync(0xffffffffu, rowacc[k], 1);
        rowacc[k] += __shfl_xor_sync(0xffffffffu, rowacc[k], 2);
    }
    if ((lane & 3) == 0) {
        int rbase = r0 + wm * 32 + (lane >> 2);
        atomicAdd(&g_rowsum[rbase],      rowacc[0]);
        atomicAdd(&g_rowsum[rbase + 8],  rowacc[1]);
        atomicAdd(&g_rowsum[rbase + 16], rowacc[2]);
        atomicAdd(&g_rowsum[rbase + 24], rowacc[3]);
    }
}

// one warp per row: positive dot, per-row loss, block reduce, fused writeout
__global__ void finish_kernel(float* __restrict__ out) {
    __shared__ float sh[8];
    int tid = threadIdx.x, lane = tid & 31, w = tid >> 5;
    int i = blockIdx.x * 8 + w;
    int j = (i + NB) & (NN - 1);
    uint2 ua = *reinterpret_cast<const uint2*>(g_Zb + (size_t)i * 256 + lane * 8);
    uint2 ub = *reinterpret_cast<const uint2*>(g_Zb + (size_t)j * 256 + lane * 8);
    float2 a0 = __bfloat1622float2(*reinterpret_cast<__nv_bfloat162*>(&ua.x));
    float2 a1 = __bfloat1622float2(*reinterpret_cast<__nv_bfloat162*>(&ua.y));
    float2 b0 = __bfloat1622float2(*reinterpret_cast<__nv_bfloat162*>(&ub.x));
    float2 b1 = __bfloat1622float2(*reinterpret_cast<__nv_bfloat162*>(&ub.y));
    float pd = a0.x*b0.x + a0.y*b0.y + a1.x*b1.x + a1.y*b1.y;
    #pragma unroll
    for (int o = 16; o; o >>= 1) pd += __shfl_xor_sync(0xffffffffu, pd, o);
    if (lane == 0) {
        float self = ex2f(fmaf(g_self[i], C1, -C1));
        sh[w] = 2.0f + logf(g_rowsum[i] - self) - 2.0f * pd;
    }
    __syncthreads();
    if (tid == 0) {
        float t = 0.f;
        #pragma unroll
        for (int k = 0; k < 8; k++) t += sh[k];
        atomicAdd(&g_loss, t);
        __threadfence();
        unsigned int done = atomicAdd(&g_done, 1u);
        if (done == (unsigned int)(gridDim.x - 1)) {
            out[0] = g_loss * (1.0f / (float)NN);
        }
    }
}

extern "C" void kernel_launch(void* const* d_in, const int* in_sizes, int n_in,
                              void* d_out, int out_size) {
    const float* zi = (const float*)d_in[0];
    const float* zj = (const float*)d_in[1];
    float* out = (float*)d_out;
    (void)in_sizes; (void)n_in; (void)out_size;

    (void)cudaFuncSetAttribute(sim_kernel,
                               cudaFuncAttributeMaxDynamicSharedMemorySize,
                               98304);

    norm_kernel<<<1024, 256>>>(zi, zj);
    sim_kernel<<<128, 256, 98304>>>();
    finish_kernel<<<NN / 8, 256>>>(out);
}